// round 2
// baseline (speedup 1.0000x reference)
#include <cuda_runtime.h>
#include <math.h>

#define NB 64
#define V 256
#define F 64
#define C 64
#define ALPHA_C 0.1f

// ---------------- scratch (no allocations allowed) ----------------
__device__ float g_pc[NB * 4 * V];   // colsum partials, 4 slots per column block
__device__ float g_pA[NB * 4 * V];   // sum tmp^2 partials
__device__ float g_pB[NB * 4 * V];   // sum tmp*d2 partials
__device__ float g_r[NB * V];        // 1/colsum
__device__ float g_lossP[NB];
__device__ float g_P[NB * V * F];    // s @ x
__device__ float g_Q[NB * V * F];    // (s*s) @ x

// upper-triangle 4x4 tile enumeration (10 tiles)
__constant__ int c_IT[10] = {0, 0, 0, 0, 1, 1, 1, 2, 2, 3};
__constant__ int c_JT[10] = {0, 1, 2, 3, 1, 2, 3, 2, 3, 3};

// ---------------- stage 1: symmetric pairwise ----------------
// Grid: (10, NB); 256 threads; 64x64 (i,j) tile, mirrored for it<jt.
__global__ __launch_bounds__(256) void pairwise_kernel(
    const float* __restrict__ x, const float* __restrict__ a,
    float* __restrict__ s_out /* tmp_s written here, normalized in pq_gemm */) {
    __shared__ float xi_t[F][68];  // [f][i] transposed; reused as transpose buf
    __shared__ float xj_t[F][68];
    __shared__ float a_s[F];
    __shared__ float smcJ[64], smAJ[64], smBJ[64];
    __shared__ float smcI[64], smAI[64], smBI[64];

    const int b = blockIdx.y;
    const int it = c_IT[blockIdx.x], jt = c_JT[blockIdx.x];
    const int i0 = it * 64, j0 = jt * 64;
    const int t = threadIdx.x;
    const bool offdiag = (it != jt);
    const float* xb = x + b * V * F;

    for (int e = t; e < 64 * F; e += 256) {
        int row = e >> 6;
        int f = e & 63;
        xi_t[f][row] = xb[(i0 + row) * F + f];
        xj_t[f][row] = xb[(j0 + row) * F + f];
    }
    if (t < F) a_s[t] = a[t];
    if (t < 64) {
        smcJ[t] = 0.f; smAJ[t] = 0.f; smBJ[t] = 0.f;
        smcI[t] = 0.f; smAI[t] = 0.f; smBI[t] = 0.f;
    }
    __syncthreads();

    const int tx = t & 15, ty = t >> 4;

    float sc[4][4], dd[4][4];
#pragma unroll
    for (int ii = 0; ii < 4; ii++)
#pragma unroll
        for (int jj = 0; jj < 4; jj++) { sc[ii][jj] = 0.f; dd[ii][jj] = 0.f; }

#pragma unroll 4
    for (int f = 0; f < F; f++) {
        float4 xi4 = *(const float4*)&xi_t[f][ty * 4];
        float4 xj4 = *(const float4*)&xj_t[f][tx * 4];
        float xiv[4] = {xi4.x, xi4.y, xi4.z, xi4.w};
        float xjv[4] = {xj4.x, xj4.y, xj4.z, xj4.w};
        float af = a_s[f];
#pragma unroll
        for (int ii = 0; ii < 4; ii++)
#pragma unroll
            for (int jj = 0; jj < 4; jj++) {
                float d = xiv[ii] - xjv[jj];
                sc[ii][jj] = fmaf(fabsf(d), af, sc[ii][jj]);
                dd[ii][jj] = fmaf(d, d, dd[ii][jj]);
            }
    }

    float tm[4][4];
    float cpart[4] = {0.f, 0.f, 0.f, 0.f};
    float Apart[4] = {0.f, 0.f, 0.f, 0.f};
    float Bpart[4] = {0.f, 0.f, 0.f, 0.f};
    float rc[4] = {0.f, 0.f, 0.f, 0.f};
    float rA[4] = {0.f, 0.f, 0.f, 0.f};
    float rB[4] = {0.f, 0.f, 0.f, 0.f};

    float* sb = s_out + (size_t)b * V * V;
#pragma unroll
    for (int ii = 0; ii < 4; ii++) {
#pragma unroll
        for (int jj = 0; jj < 4; jj++) {
            float tmp = expf(-fmaxf(sc[ii][jj], 0.f));
            tm[ii][jj] = tmp;
            float t2 = tmp * tmp;
            float td = tmp * dd[ii][jj];
            cpart[jj] += tmp; Apart[jj] += t2; Bpart[jj] += td;
            rc[ii] += tmp;    rA[ii] += t2;    rB[ii] += td;
        }
        *(float4*)&sb[(i0 + ty * 4 + ii) * V + j0 + tx * 4] =
            make_float4(tm[ii][0], tm[ii][1], tm[ii][2], tm[ii][3]);
    }

#pragma unroll
    for (int jj = 0; jj < 4; jj++) {
        atomicAdd(&smcJ[tx * 4 + jj], cpart[jj]);
        atomicAdd(&smAJ[tx * 4 + jj], Apart[jj]);
        atomicAdd(&smBJ[tx * 4 + jj], Bpart[jj]);
    }
    if (offdiag) {
#pragma unroll
        for (int ii = 0; ii < 4; ii++) {
            atomicAdd(&smcI[ty * 4 + ii], rc[ii]);
            atomicAdd(&smAI[ty * 4 + ii], rA[ii]);
            atomicAdd(&smBI[ty * 4 + ii], rB[ii]);
        }
    }
    __syncthreads();

    if (t < 64) {
        // col-stats of column block jt -> slot it
        int bc = (b * 4 + it) * V + j0 + t;
        g_pc[bc] = smcJ[t]; g_pA[bc] = smAJ[t]; g_pB[bc] = smBJ[t];
        if (offdiag) {
            // row-stats = col-stats of column block it (symmetry) -> slot jt
            int br = (b * 4 + jt) * V + i0 + t;
            g_pc[br] = smcI[t]; g_pA[br] = smAI[t]; g_pB[br] = smBI[t];
        }
    }

    // mirror write for off-diagonal tiles via smem transpose (reuse xi_t)
    if (offdiag) {
        // all reads of xi_t finished (sync above)
#pragma unroll
        for (int jj = 0; jj < 4; jj++) {
            *(float4*)&xi_t[tx * 4 + jj][ty * 4] =
                make_float4(tm[0][jj], tm[1][jj], tm[2][jj], tm[3][jj]);
        }
        __syncthreads();
        for (int e = t; e < 64 * 16; e += 256) {
            int row = e >> 4;
            int c4 = (e & 15) * 4;
            *(float4*)&sb[(j0 + row) * V + i0 + c4] = *(float4*)&xi_t[row][c4];
        }
    }
}

// ---------------- stage 2: sum 4 slots, recip, per-batch loss partial ----------------
__global__ void colstats_kernel() {
    int b = blockIdx.x;
    int j = threadIdx.x;  // 256 threads
    float cs = 0.f, A = 0.f, B = 0.f;
#pragma unroll
    for (int s = 0; s < 4; s++) {
        int idx = (b * 4 + s) * V + j;
        cs += g_pc[idx]; A += g_pA[idx]; B += g_pB[idx];
    }
    float r = 1.0f / cs;
    g_r[b * V + j] = r;
    float part = A * r * r + ALPHA_C * B * r;
    __shared__ float red[256];
    red[j] = part;
    __syncthreads();
    for (int s = 128; s > 0; s >>= 1) {
        if (j < s) red[j] += red[j + s];
        __syncthreads();
    }
    if (j == 0) g_lossP[b] = red[0];
}

// ---------------- stage 3: P = s@x, Q = (s*s)@x + fused normalization ----------------
// Grid: (it=4, b=64); 256 threads; reads tmp_s, scales by r[k], writes back normalized s.
__global__ __launch_bounds__(256) void pq_gemm_kernel(
    float* __restrict__ s_out, const float* __restrict__ x) {
    __shared__ float sA[64][68];  // normalized s chunk transposed [k][i]
    __shared__ float sB[64][64];  // x chunk natural [k][f]

    const int b = blockIdx.y, it = blockIdx.x;
    const int i0 = it * 64;
    const int t = threadIdx.x;
    const int tx = t & 15, ty = t >> 4;

    float* sb = s_out + (size_t)b * V * V;
    const float* xb = x + b * V * F;

    float P[4][4], Q[4][4];
#pragma unroll
    for (int ii = 0; ii < 4; ii++)
#pragma unroll
        for (int jj = 0; jj < 4; jj++) { P[ii][jj] = 0.f; Q[ii][jj] = 0.f; }

    for (int kc = 0; kc < 4; kc++) {
        int k0 = kc * 64;
        for (int q = t; q < 64 * 16; q += 256) {
            int i = q >> 4;
            int k4 = (q & 15) * 4;
            float* addr = &sb[(i0 + i) * V + k0 + k4];
            float4 v = *(const float4*)addr;
            float4 rv = *(const float4*)&g_r[b * V + k0 + k4];
            v.x *= rv.x; v.y *= rv.y; v.z *= rv.z; v.w *= rv.w;
            *(float4*)addr = v;  // write back normalized s (each element touched once)
            sA[k4 + 0][i] = v.x;
            sA[k4 + 1][i] = v.y;
            sA[k4 + 2][i] = v.z;
            sA[k4 + 3][i] = v.w;
        }
        for (int q = t; q < 64 * 16; q += 256) {
            int k = q >> 4;
            int f4 = (q & 15) * 4;
            *(float4*)&sB[k][f4] = *(const float4*)&xb[(k0 + k) * F + f4];
        }
        __syncthreads();
#pragma unroll 4
        for (int k = 0; k < 64; k++) {
            float4 a4 = *(const float4*)&sA[k][ty * 4];
            float4 b4 = *(const float4*)&sB[k][tx * 4];
            float av[4] = {a4.x, a4.y, a4.z, a4.w};
            float bv[4] = {b4.x, b4.y, b4.z, b4.w};
            float a2[4];
#pragma unroll
            for (int u = 0; u < 4; u++) a2[u] = av[u] * av[u];
#pragma unroll
            for (int ii = 0; ii < 4; ii++)
#pragma unroll
                for (int jj = 0; jj < 4; jj++) {
                    P[ii][jj] = fmaf(av[ii], bv[jj], P[ii][jj]);
                    Q[ii][jj] = fmaf(a2[ii], bv[jj], Q[ii][jj]);
                }
        }
        __syncthreads();
    }

    float* pOut = g_P + b * V * F;
    float* qOut = g_Q + b * V * F;
#pragma unroll
    for (int ii = 0; ii < 4; ii++) {
        int row = i0 + ty * 4 + ii;
        *(float4*)&pOut[row * F + tx * 4] = make_float4(P[ii][0], P[ii][1], P[ii][2], P[ii][3]);
        *(float4*)&qOut[row * F + tx * 4] = make_float4(Q[ii][0], Q[ii][1], Q[ii][2], Q[ii][3]);
    }
}

// ---------------- stage 4: out = relu( x@(th0-th2) - P@th1 + Q@(2*th2) ) + loss ----------------
__global__ __launch_bounds__(256) void out_gemm_kernel(
    const float* __restrict__ x, const float* __restrict__ theta,
    float* __restrict__ gcn, float* __restrict__ out_loss) {
    __shared__ float sTh[64][64];   // [f][c]
    __shared__ float sSrc[64][68];  // [f][i]

    const int b = blockIdx.y, it = blockIdx.x;
    const int i0 = it * 64;
    const int t = threadIdx.x;
    const int tx = t & 15, ty = t >> 4;

    // fold final loss reduction into one thread of one block
    if (b == 0 && it == 0 && t == 0) {
        float acc = 0.f;
#pragma unroll
        for (int i = 0; i < NB; i++) acc += g_lossP[i];
        *out_loss = acc;
    }

    float acc[4][4];
#pragma unroll
    for (int ii = 0; ii < 4; ii++)
#pragma unroll
        for (int jj = 0; jj < 4; jj++) acc[ii][jj] = 0.f;

    for (int m = 0; m < 3; m++) {
        const float* src = (m == 0) ? (x + b * V * F)
                         : (m == 1) ? (g_P + b * V * F)
                                    : (g_Q + b * V * F);
        for (int q = t; q < 64 * 16; q += 256) {
            int f = q >> 4;
            int c4 = (q & 15) * 4;
            float4 v;
            if (m == 0) {
                float4 t0 = *(const float4*)&theta[(0 * F + f) * C + c4];
                float4 t2 = *(const float4*)&theta[(2 * F + f) * C + c4];
                v = make_float4(t0.x - t2.x, t0.y - t2.y, t0.z - t2.z, t0.w - t2.w);
            } else if (m == 1) {
                float4 t1 = *(const float4*)&theta[(1 * F + f) * C + c4];
                v = make_float4(-t1.x, -t1.y, -t1.z, -t1.w);
            } else {
                float4 t2 = *(const float4*)&theta[(2 * F + f) * C + c4];
                v = make_float4(2.f * t2.x, 2.f * t2.y, 2.f * t2.z, 2.f * t2.w);
            }
            *(float4*)&sTh[f][c4] = v;
        }
        for (int q = t; q < 64 * 16; q += 256) {
            int i = q >> 4;
            int f4 = (q & 15) * 4;
            float4 v = *(const float4*)&src[(i0 + i) * F + f4];
            sSrc[f4 + 0][i] = v.x;
            sSrc[f4 + 1][i] = v.y;
            sSrc[f4 + 2][i] = v.z;
            sSrc[f4 + 3][i] = v.w;
        }
        __syncthreads();
#pragma unroll 4
        for (int k = 0; k < 64; k++) {
            float4 a4 = *(const float4*)&sSrc[k][ty * 4];
            float4 b4 = *(const float4*)&sTh[k][tx * 4];
            float av[4] = {a4.x, a4.y, a4.z, a4.w};
            float bv[4] = {b4.x, b4.y, b4.z, b4.w};
#pragma unroll
            for (int ii = 0; ii < 4; ii++)
#pragma unroll
                for (int jj = 0; jj < 4; jj++)
                    acc[ii][jj] = fmaf(av[ii], bv[jj], acc[ii][jj]);
        }
        __syncthreads();
    }

#pragma unroll
    for (int ii = 0; ii < 4; ii++) {
        int row = i0 + ty * 4 + ii;
        float4 o = make_float4(fmaxf(acc[ii][0], 0.f), fmaxf(acc[ii][1], 0.f),
                               fmaxf(acc[ii][2], 0.f), fmaxf(acc[ii][3], 0.f));
        *(float4*)&gcn[b * V * C + row * C + tx * 4] = o;
    }
}

// ---------------- launch ----------------
extern "C" void kernel_launch(void* const* d_in, const int* in_sizes, int n_in,
                              void* d_out, int out_size) {
    const float* x = (const float*)d_in[0];      // (64,256,64)
    const float* a = (const float*)d_in[1];      // (64,)
    const float* theta = (const float*)d_in[2];  // (3,64,64)

    float* out = (float*)d_out;
    float* gcn = out;                                 // NB*V*C
    float* s_out = out + (size_t)NB * V * C;          // NB*V*V
    float* loss = out + (size_t)NB * V * C + (size_t)NB * V * V;  // 1

    dim3 g1(10, NB);
    pairwise_kernel<<<g1, 256>>>(x, a, s_out);

    colstats_kernel<<<NB, 256>>>();

    dim3 g4(4, NB);
    pq_gemm_kernel<<<g4, 256>>>(s_out, x);

    dim3 g5(4, NB);
    out_gemm_kernel<<<g5, 256>>>(x, theta, gcn, loss);
}

// round 3
// speedup vs baseline: 1.0847x; 1.0847x over previous
#include <cuda_runtime.h>
#include <math.h>

#define NB 64
#define V 256
#define F 64
#define C 64
#define ALPHA_C 0.1f
#define YSZ (NB * V * F)

// ---------------- scratch (no allocations allowed) ----------------
__device__ float g_pc[NB * 4 * V];   // colsum partials, 4 slots per column block
__device__ float g_pA[NB * 4 * V];   // sum tmp^2 partials
__device__ float g_pB[NB * 4 * V];   // sum tmp*d2 partials
__device__ float g_r[NB * V];        // 1/colsum
__device__ float g_lossP[NB];
__device__ float g_Y[3 * YSZ];       // Y0 = x@(th0-th2), Y1 = x@(-th1), Y2 = x@(2*th2)

// upper-triangle 4x4 tile enumeration (10 tiles)
__constant__ int c_IT[10] = {0, 0, 0, 0, 1, 1, 1, 2, 2, 3};
__constant__ int c_JT[10] = {0, 1, 2, 3, 1, 2, 3, 2, 3, 3};

// ---------------- kernel A: Y0/Y1/Y2 = x @ combined-thetas ----------------
// Grid: (4 it, 64 b); 256 threads; x tile loaded once, 3 accumulator sets.
__global__ __launch_bounds__(256) void y_gemm_kernel(
    const float* __restrict__ x, const float* __restrict__ theta) {
    __shared__ float sW0[64][64];
    __shared__ float sW1[64][64];
    __shared__ float sW2[64][64];
    __shared__ float sX[64][68];  // [f][i]

    const int b = blockIdx.y, it = blockIdx.x;
    const int i0 = it * 64;
    const int t = threadIdx.x;
    const int tx = t & 15, ty = t >> 4;
    const float* xb = x + b * V * F;

    for (int q = t; q < 64 * 16; q += 256) {
        int f = q >> 4;
        int c4 = (q & 15) * 4;
        float4 t0 = *(const float4*)&theta[(0 * F + f) * C + c4];
        float4 t1 = *(const float4*)&theta[(1 * F + f) * C + c4];
        float4 t2 = *(const float4*)&theta[(2 * F + f) * C + c4];
        *(float4*)&sW0[f][c4] = make_float4(t0.x - t2.x, t0.y - t2.y, t0.z - t2.z, t0.w - t2.w);
        *(float4*)&sW1[f][c4] = make_float4(-t1.x, -t1.y, -t1.z, -t1.w);
        *(float4*)&sW2[f][c4] = make_float4(2.f * t2.x, 2.f * t2.y, 2.f * t2.z, 2.f * t2.w);
    }
    for (int q = t; q < 64 * 16; q += 256) {
        int i = q >> 4;
        int f4 = (q & 15) * 4;
        float4 v = *(const float4*)&xb[(i0 + i) * F + f4];
        sX[f4 + 0][i] = v.x;
        sX[f4 + 1][i] = v.y;
        sX[f4 + 2][i] = v.z;
        sX[f4 + 3][i] = v.w;
    }
    __syncthreads();

    float a0[4][4], a1[4][4], a2[4][4];
#pragma unroll
    for (int ii = 0; ii < 4; ii++)
#pragma unroll
        for (int jj = 0; jj < 4; jj++) { a0[ii][jj] = 0.f; a1[ii][jj] = 0.f; a2[ii][jj] = 0.f; }

#pragma unroll 4
    for (int k = 0; k < 64; k++) {
        float4 xa = *(const float4*)&sX[k][ty * 4];
        float4 w0 = *(const float4*)&sW0[k][tx * 4];
        float4 w1 = *(const float4*)&sW1[k][tx * 4];
        float4 w2 = *(const float4*)&sW2[k][tx * 4];
        float xv[4] = {xa.x, xa.y, xa.z, xa.w};
        float w0v[4] = {w0.x, w0.y, w0.z, w0.w};
        float w1v[4] = {w1.x, w1.y, w1.z, w1.w};
        float w2v[4] = {w2.x, w2.y, w2.z, w2.w};
#pragma unroll
        for (int ii = 0; ii < 4; ii++)
#pragma unroll
            for (int jj = 0; jj < 4; jj++) {
                a0[ii][jj] = fmaf(xv[ii], w0v[jj], a0[ii][jj]);
                a1[ii][jj] = fmaf(xv[ii], w1v[jj], a1[ii][jj]);
                a2[ii][jj] = fmaf(xv[ii], w2v[jj], a2[ii][jj]);
            }
    }

    float* y0 = g_Y + 0 * YSZ + b * V * F;
    float* y1 = g_Y + 1 * YSZ + b * V * F;
    float* y2 = g_Y + 2 * YSZ + b * V * F;
#pragma unroll
    for (int ii = 0; ii < 4; ii++) {
        int row = i0 + ty * 4 + ii;
        *(float4*)&y0[row * F + tx * 4] = make_float4(a0[ii][0], a0[ii][1], a0[ii][2], a0[ii][3]);
        *(float4*)&y1[row * F + tx * 4] = make_float4(a1[ii][0], a1[ii][1], a1[ii][2], a1[ii][3]);
        *(float4*)&y2[row * F + tx * 4] = make_float4(a2[ii][0], a2[ii][1], a2[ii][2], a2[ii][3]);
    }
}

// ---------------- stage 1: symmetric pairwise ----------------
// Grid: (10, NB); 256 threads; 64x64 (i,j) tile, mirrored for it<jt.
__global__ __launch_bounds__(256) void pairwise_kernel(
    const float* __restrict__ x, const float* __restrict__ a,
    float* __restrict__ s_out /* tmp_s written here, normalized in fused kernel */) {
    __shared__ float xi_t[F][68];  // [f][i] transposed; reused as transpose buf
    __shared__ float xj_t[F][68];
    __shared__ float a_s[F];
    __shared__ float smcJ[64], smAJ[64], smBJ[64];
    __shared__ float smcI[64], smAI[64], smBI[64];

    const int b = blockIdx.y;
    const int it = c_IT[blockIdx.x], jt = c_JT[blockIdx.x];
    const int i0 = it * 64, j0 = jt * 64;
    const int t = threadIdx.x;
    const bool offdiag = (it != jt);
    const float* xb = x + b * V * F;

    for (int e = t; e < 64 * F; e += 256) {
        int row = e >> 6;
        int f = e & 63;
        xi_t[f][row] = xb[(i0 + row) * F + f];
        xj_t[f][row] = xb[(j0 + row) * F + f];
    }
    if (t < F) a_s[t] = a[t];
    if (t < 64) {
        smcJ[t] = 0.f; smAJ[t] = 0.f; smBJ[t] = 0.f;
        smcI[t] = 0.f; smAI[t] = 0.f; smBI[t] = 0.f;
    }
    __syncthreads();

    const int tx = t & 15, ty = t >> 4;

    float sc[4][4], dd[4][4];
#pragma unroll
    for (int ii = 0; ii < 4; ii++)
#pragma unroll
        for (int jj = 0; jj < 4; jj++) { sc[ii][jj] = 0.f; dd[ii][jj] = 0.f; }

#pragma unroll 4
    for (int f = 0; f < F; f++) {
        float4 xi4 = *(const float4*)&xi_t[f][ty * 4];
        float4 xj4 = *(const float4*)&xj_t[f][tx * 4];
        float xiv[4] = {xi4.x, xi4.y, xi4.z, xi4.w};
        float xjv[4] = {xj4.x, xj4.y, xj4.z, xj4.w};
        float af = a_s[f];
#pragma unroll
        for (int ii = 0; ii < 4; ii++)
#pragma unroll
            for (int jj = 0; jj < 4; jj++) {
                float d = xiv[ii] - xjv[jj];
                sc[ii][jj] = fmaf(fabsf(d), af, sc[ii][jj]);
                dd[ii][jj] = fmaf(d, d, dd[ii][jj]);
            }
    }

    float tm[4][4];
    float cpart[4] = {0.f, 0.f, 0.f, 0.f};
    float Apart[4] = {0.f, 0.f, 0.f, 0.f};
    float Bpart[4] = {0.f, 0.f, 0.f, 0.f};
    float rc[4] = {0.f, 0.f, 0.f, 0.f};
    float rA[4] = {0.f, 0.f, 0.f, 0.f};
    float rB[4] = {0.f, 0.f, 0.f, 0.f};

    float* sb = s_out + (size_t)b * V * V;
#pragma unroll
    for (int ii = 0; ii < 4; ii++) {
#pragma unroll
        for (int jj = 0; jj < 4; jj++) {
            float tmp = __expf(-fmaxf(sc[ii][jj], 0.f));
            tm[ii][jj] = tmp;
            float t2 = tmp * tmp;
            float td = tmp * dd[ii][jj];
            cpart[jj] += tmp; Apart[jj] += t2; Bpart[jj] += td;
            rc[ii] += tmp;    rA[ii] += t2;    rB[ii] += td;
        }
        *(float4*)&sb[(i0 + ty * 4 + ii) * V + j0 + tx * 4] =
            make_float4(tm[ii][0], tm[ii][1], tm[ii][2], tm[ii][3]);
    }

#pragma unroll
    for (int jj = 0; jj < 4; jj++) {
        atomicAdd(&smcJ[tx * 4 + jj], cpart[jj]);
        atomicAdd(&smAJ[tx * 4 + jj], Apart[jj]);
        atomicAdd(&smBJ[tx * 4 + jj], Bpart[jj]);
    }
    if (offdiag) {
#pragma unroll
        for (int ii = 0; ii < 4; ii++) {
            atomicAdd(&smcI[ty * 4 + ii], rc[ii]);
            atomicAdd(&smAI[ty * 4 + ii], rA[ii]);
            atomicAdd(&smBI[ty * 4 + ii], rB[ii]);
        }
    }
    __syncthreads();

    if (t < 64) {
        // col-stats of column block jt -> slot it
        int bc = (b * 4 + it) * V + j0 + t;
        g_pc[bc] = smcJ[t]; g_pA[bc] = smAJ[t]; g_pB[bc] = smBJ[t];
        if (offdiag) {
            // row-stats = col-stats of column block it (symmetry) -> slot jt
            int br = (b * 4 + jt) * V + i0 + t;
            g_pc[br] = smcI[t]; g_pA[br] = smAI[t]; g_pB[br] = smBI[t];
        }
    }

    // mirror write for off-diagonal tiles via smem transpose (reuse xi_t)
    if (offdiag) {
#pragma unroll
        for (int jj = 0; jj < 4; jj++) {
            *(float4*)&xi_t[tx * 4 + jj][ty * 4] =
                make_float4(tm[0][jj], tm[1][jj], tm[2][jj], tm[3][jj]);
        }
        __syncthreads();
        for (int e = t; e < 64 * 16; e += 256) {
            int row = e >> 4;
            int c4 = (e & 15) * 4;
            *(float4*)&sb[(j0 + row) * V + i0 + c4] = *(float4*)&xi_t[row][c4];
        }
    }
}

// ---------------- stage 2: sum 4 slots, recip, per-batch loss partial ----------------
__global__ void colstats_kernel() {
    int b = blockIdx.x;
    int j = threadIdx.x;  // 256 threads
    float cs = 0.f, A = 0.f, B = 0.f;
#pragma unroll
    for (int s = 0; s < 4; s++) {
        int idx = (b * 4 + s) * V + j;
        cs += g_pc[idx]; A += g_pA[idx]; B += g_pB[idx];
    }
    float r = 1.0f / cs;
    g_r[b * V + j] = r;
    float part = A * r * r + ALPHA_C * B * r;
    __shared__ float red[256];
    red[j] = part;
    __syncthreads();
    for (int s = 128; s > 0; s >>= 1) {
        if (j < s) red[j] += red[j + s];
        __syncthreads();
    }
    if (j == 0) g_lossP[b] = red[0];
}

// ---------------- stage 3 (fused): gcn = relu(Y0 + s@Y1 + (s*s)@Y2), normalize s ----------------
// Grid: (it=4, b=64); 256 threads; reads tmp_s once, scales by r[k], writes back
// normalized s, single accumulator set seeded with Y0. Also folds final loss sum.
__global__ __launch_bounds__(256) void fused_gemm_kernel(
    float* __restrict__ s_out, float* __restrict__ gcn, float* __restrict__ out_loss) {
    __shared__ float sA[64][68];   // normalized s chunk transposed [k][i]
    __shared__ float sY1[64][64];  // Y1 chunk [k][c]
    __shared__ float sY2[64][64];  // Y2 chunk [k][c]

    const int b = blockIdx.y, it = blockIdx.x;
    const int i0 = it * 64;
    const int t = threadIdx.x;
    const int tx = t & 15, ty = t >> 4;

    if (b == 0 && it == 0 && t == 0) {
        float acc = 0.f;
#pragma unroll
        for (int i = 0; i < NB; i++) acc += g_lossP[i];
        *out_loss = acc;
    }

    float* sb = s_out + (size_t)b * V * V;
    const float* y0 = g_Y + 0 * YSZ + b * V * F;
    const float* y1 = g_Y + 1 * YSZ + b * V * F;
    const float* y2 = g_Y + 2 * YSZ + b * V * F;

    float acc[4][4];
#pragma unroll
    for (int ii = 0; ii < 4; ii++) {
        float4 v = *(const float4*)&y0[(i0 + ty * 4 + ii) * F + tx * 4];
        acc[ii][0] = v.x; acc[ii][1] = v.y; acc[ii][2] = v.z; acc[ii][3] = v.w;
    }

    for (int kc = 0; kc < 4; kc++) {
        int k0 = kc * 64;
        for (int q = t; q < 64 * 16; q += 256) {
            int i = q >> 4;
            int k4 = (q & 15) * 4;
            float* addr = &sb[(i0 + i) * V + k0 + k4];
            float4 v = *(const float4*)addr;
            float4 rv = *(const float4*)&g_r[b * V + k0 + k4];
            v.x *= rv.x; v.y *= rv.y; v.z *= rv.z; v.w *= rv.w;
            *(float4*)addr = v;  // write back normalized s
            sA[k4 + 0][i] = v.x;
            sA[k4 + 1][i] = v.y;
            sA[k4 + 2][i] = v.z;
            sA[k4 + 3][i] = v.w;
        }
        for (int q = t; q < 64 * 16; q += 256) {
            int k = q >> 4;
            int f4 = (q & 15) * 4;
            *(float4*)&sY1[k][f4] = *(const float4*)&y1[(k0 + k) * F + f4];
            *(float4*)&sY2[k][f4] = *(const float4*)&y2[(k0 + k) * F + f4];
        }
        __syncthreads();
#pragma unroll 4
        for (int k = 0; k < 64; k++) {
            float4 a4 = *(const float4*)&sA[k][ty * 4];
            float4 b1 = *(const float4*)&sY1[k][tx * 4];
            float4 b2 = *(const float4*)&sY2[k][tx * 4];
            float av[4] = {a4.x, a4.y, a4.z, a4.w};
            float b1v[4] = {b1.x, b1.y, b1.z, b1.w};
            float b2v[4] = {b2.x, b2.y, b2.z, b2.w};
            float a2[4];
#pragma unroll
            for (int u = 0; u < 4; u++) a2[u] = av[u] * av[u];
#pragma unroll
            for (int ii = 0; ii < 4; ii++)
#pragma unroll
                for (int jj = 0; jj < 4; jj++) {
                    acc[ii][jj] = fmaf(av[ii], b1v[jj], acc[ii][jj]);
                    acc[ii][jj] = fmaf(a2[ii], b2v[jj], acc[ii][jj]);
                }
        }
        __syncthreads();
    }

#pragma unroll
    for (int ii = 0; ii < 4; ii++) {
        int row = i0 + ty * 4 + ii;
        float4 o = make_float4(fmaxf(acc[ii][0], 0.f), fmaxf(acc[ii][1], 0.f),
                               fmaxf(acc[ii][2], 0.f), fmaxf(acc[ii][3], 0.f));
        *(float4*)&gcn[b * V * C + row * C + tx * 4] = o;
    }
}

// ---------------- launch ----------------
extern "C" void kernel_launch(void* const* d_in, const int* in_sizes, int n_in,
                              void* d_out, int out_size) {
    const float* x = (const float*)d_in[0];      // (64,256,64)
    const float* a = (const float*)d_in[1];      // (64,)
    const float* theta = (const float*)d_in[2];  // (3,64,64)

    float* out = (float*)d_out;
    float* gcn = out;                                 // NB*V*C
    float* s_out = out + (size_t)NB * V * C;          // NB*V*V
    float* loss = out + (size_t)NB * V * C + (size_t)NB * V * V;  // 1

    dim3 gA(4, NB);
    y_gemm_kernel<<<gA, 256>>>(x, theta);

    dim3 g1(10, NB);
    pairwise_kernel<<<g1, 256>>>(x, a, s_out);

    colstats_kernel<<<NB, 256>>>();

    dim3 gB(4, NB);
    fused_gemm_kernel<<<gB, 256>>>(s_out, gcn, loss);
}